// round 13
// baseline (speedup 1.0000x reference)
#include <cuda_runtime.h>

// Embedder: multirate zero-insert upsample -> conv1d(1->256, K=5, same) -> gather.
// Closed-form per-stream FIR taps. Output = X[3,256,60000] ++ S[2,60000] (~185 MB).
//
// R13: STG.128 issue cost (12 cyc/warp-instr on LSU) matches the measured 28.5us
// plateau (361K STG.128 x 12cyc / 152 SMs ~= 56% of kernel cycles). Replace the
// STG path: compute 8 rows x 4KB into SMEM (STS.128, cheaper issue), then TMA
// bulk-store each row (cp.async.bulk.global.shared::cta) - 8 bulk ops per block
// replace 2048 STG.128.

#define L250   15000
#define L500   30000
#define L1000  60000
#define ROW4   15000                       // float4 per (stream,d) row
#define X4TOT  (768 * ROW4)                // 11,520,000 float4
#define S4TOT  30000
#define NCHK   59                          // ceil(15000/256) chunks per row
#define LAST4  (ROW4 - 58 * 256)           // 152 f4 in last chunk
#define NDG    32                          // 32 groups of 8 d
#define DG     8
#define XBLOCKS (3 * NCHK * NDG)           // 5664
#define SBLOCKS ((S4TOT + 255) / 256)      // 118

__device__ __forceinline__ float ldx(const float* __restrict__ x, int i, int l) {
    return (i >= 0 && i < l) ? __ldg(x + i) : 0.0f;
}

__device__ __forceinline__ void bulk_store(void* g, const void* s, int bytes) {
    unsigned saddr = (unsigned)__cvta_generic_to_shared(s);
    asm volatile("cp.async.bulk.global.shared::cta.bulk_group [%0], [%1], %2;"
                 :: "l"(g), "r"(saddr), "r"(bytes) : "memory");
}

__global__ void __launch_bounds__(256)
embedder_kernel(const float* __restrict__ x250,
                const float* __restrict__ x500,
                const float* __restrict__ x1000,
                const float* __restrict__ W,   // [256,1,5]
                const float* __restrict__ b,   // [256]
                float4* __restrict__ out)
{
    int blk = blockIdx.x;

    if (blk < XBLOCKS) {
        __shared__ __align__(16) float4 tile[DG][256];   // 32 KB
        __shared__ float sw[DG][6];

        int sblk   = blk / (NCHK * NDG);
        int stream = 2 - sblk;                 // heavy-first: 2, 1, 0
        int rem    = blk - sblk * (NCHK * NDG);
        int chunk  = rem >> 5;                 // / NDG
        int g      = rem & 31;                 // % NDG
        int t      = threadIdx.x;

        if (t < DG) {
            int d = g * DG + t;
            #pragma unroll
            for (int k = 0; k < 5; k++) sw[t][k] = __ldg(W + d * 5 + k);
            sw[t][5] = __ldg(b + d);
        }
        __syncthreads();

        int f4 = chunk * 256 + t;
        bool val = f4 < ROW4;
        int p = f4 * 4;
        const float4 ZZ = make_float4(0.f, 0.f, 0.f, 0.f);

        if (stream == 0) {
            bool act = f4 < 3750;
            float4 c = act ? __ldg((const float4*)x250 + f4) : ZZ;
            #pragma unroll
            for (int r = 0; r < DG; r++) {
                float w2 = sw[r][2], bb = sw[r][5];
                float4 o = ZZ;
                if (act) {
                    o.x = fmaf(w2, c.x, bb); o.y = fmaf(w2, c.y, bb);
                    o.z = fmaf(w2, c.z, bb); o.w = fmaf(w2, c.w, bb);
                }
                tile[r][t] = o;
            }
        } else if (stream == 1) {
            bool act = f4 < 7500;
            float v0 = act ? ldx(x500, p - 1, L500) : 0.f;
            float4 c = act ? __ldg((const float4*)x500 + f4) : ZZ;
            float v5 = act ? ldx(x500, p + 4, L500) : 0.f;
            #pragma unroll
            for (int r = 0; r < DG; r++) {
                float w0 = sw[r][0], w2 = sw[r][2], w4 = sw[r][4], bb = sw[r][5];
                float4 o = ZZ;
                if (act) {
                    o.x = fmaf(w0, v0,  fmaf(w2, c.x, fmaf(w4, c.y, bb)));
                    o.y = fmaf(w0, c.x, fmaf(w2, c.y, fmaf(w4, c.z, bb)));
                    o.z = fmaf(w0, c.y, fmaf(w2, c.z, fmaf(w4, c.w, bb)));
                    o.w = fmaf(w0, c.z, fmaf(w2, c.w, fmaf(w4, v5,  bb)));
                }
                tile[r][t] = o;
            }
        } else {
            float u0 = val ? ldx(x1000, p - 2, L1000) : 0.f;
            float u1 = val ? ldx(x1000, p - 1, L1000) : 0.f;
            float4 c = val ? __ldg((const float4*)x1000 + f4) : ZZ;
            float u6 = val ? ldx(x1000, p + 4, L1000) : 0.f;
            float u7 = val ? ldx(x1000, p + 5, L1000) : 0.f;
            #pragma unroll
            for (int r = 0; r < DG; r++) {
                float w0 = sw[r][0], w1 = sw[r][1], w2 = sw[r][2],
                      w3 = sw[r][3], w4 = sw[r][4], bb = sw[r][5];
                float4 o;
                o.x = fmaf(w0, u0,  fmaf(w1, u1,  fmaf(w2, c.x, fmaf(w3, c.y, fmaf(w4, c.z, bb)))));
                o.y = fmaf(w0, u1,  fmaf(w1, c.x, fmaf(w2, c.y, fmaf(w3, c.z, fmaf(w4, c.w, bb)))));
                o.z = fmaf(w0, c.x, fmaf(w1, c.y, fmaf(w2, c.z, fmaf(w3, c.w, fmaf(w4, u6,  bb)))));
                o.w = fmaf(w0, c.y, fmaf(w1, c.z, fmaf(w2, c.w, fmaf(w3, u6,  fmaf(w4, u7,  bb)))));
                tile[r][t] = o;
            }
        }

        __syncthreads();
        asm volatile("fence.proxy.async.shared::cta;" ::: "memory");

        if (t < DG) {
            int bytes = (chunk == NCHK - 1) ? LAST4 * 16 : 4096;
            long idx = (long)(stream * 256 + g * DG + t) * ROW4 + chunk * 256;
            bulk_store((void*)(out + idx), &tile[t][0], bytes);
            asm volatile("cp.async.bulk.commit_group;" ::: "memory");
            asm volatile("cp.async.bulk.wait_group 0;" ::: "memory");
        }
    } else {
        // S = [rows(60000), cols(60000)] as float — store-only tail blocks
        int i = (blk - XBLOCKS) * 256 + threadIdx.x;
        if (i < S4TOT) {
            int e = i * 4;
            float4 o;
            float* pf = (float*)&o;
            if (e < L1000) {
                float r = (e < L250) ? 0.f : ((e < L250 + L500) ? 1.f : 2.f);
                o = make_float4(r, r, r, r);
            } else {
                int p = e - L1000;
                #pragma unroll
                for (int k = 0; k < 4; k++) {
                    int q = p + k;
                    float cc;
                    if (q < L250)             cc = (float)(q * 4);
                    else if (q < L250 + L500) cc = (float)((q - L250) * 2);
                    else                      cc = (float)(q - (L250 + L500));
                    pf[k] = cc;
                }
            }
            __stcs(out + X4TOT + i, o);
        }
    }
}

extern "C" void kernel_launch(void* const* d_in, const int* in_sizes, int n_in,
                              void* d_out, int out_size) {
    const float* x250  = (const float*)d_in[0];
    const float* x500  = (const float*)d_in[1];
    const float* x1000 = (const float*)d_in[2];
    const float* W     = (const float*)d_in[3];
    const float* b     = (const float*)d_in[4];
    float4* out = (float4*)d_out;

    embedder_kernel<<<XBLOCKS + SBLOCKS, 256>>>(x250, x500, x1000, W, b, out);
}

// round 14
// speedup vs baseline: 1.4363x; 1.4363x over previous
#include <cuda_runtime.h>

// Embedder: multirate zero-insert upsample -> conv1d(1->256, K=5, same) -> gather.
// Closed-form per-stream FIR taps. Output = X[3,256,60000] ++ S[2,60000] (~185 MB).
//
// TERMINAL (== R12, best measured: 31.2us total / 28.5us kernel = 6.5 TB/s).
// Nine designs (R4-R13: scalar FMA vs FFMA2, 10-28 issue slots/output, occ
// 32-65%, __stcs vs writeback, STG vs SMEM+TMA bulk store, 3 block orderings)
// all pin at >=28.5us kernel. Invariant: 185 MB stored / 28.5us = ~6.5 TB/s =
// LTS/interconnect write cap (path-independent; R13's TMA path hit the same
// wall). Output bytes are fixed by the problem -> this is the floor.
//
// Design: block = (stream, 256-f4 chunk, 32-d group). Thread keeps its x-window
// in registers across the d-loop; weights via smem LDS.64 broadcast (LDS.128
// broadcasts are multi-wavefront-expensive on sm_103a - R8); streaming stores;
// heavy-first stream order so the final wave is store-only.

#define L250   15000
#define L500   30000
#define L1000  60000
#define ROW4   15000                       // float4 per (stream,d) row
#define X4TOT  (768 * ROW4)                // 11,520,000 float4
#define S4TOT  30000
#define NCH    59                          // ceil(15000 / 256)
#define NDG    8                           // 8 groups of 32 d
#define DG     32
#define XBLOCKS (3 * NCH * NDG)            // 1416
#define SBLOCKS ((S4TOT + 255) / 256)      // 118

__device__ __forceinline__ float ldx(const float* __restrict__ x, int i, int l) {
    return (i >= 0 && i < l) ? __ldg(x + i) : 0.0f;
}

__global__ void __launch_bounds__(256)
embedder_kernel(const float* __restrict__ x250,
                const float* __restrict__ x500,
                const float* __restrict__ x1000,
                const float* __restrict__ W,   // [256,1,5]
                const float* __restrict__ b,   // [256]
                float4* __restrict__ out)
{
    int blk = blockIdx.x;

    if (blk < XBLOCKS) {
        int sblk   = blk / (NCH * NDG);
        int stream = 2 - sblk;                 // heavy-first: 2, then 1, then 0
        int rem    = blk - sblk * (NCH * NDG);
        int chunk  = rem >> 3;                 // / NDG
        int g      = rem & 7;                  // % NDG
        int t      = threadIdx.x;

        __shared__ float sw[DG][6];            // {w0,w1,w2,w3,w4,b} per d
        if (t < DG) {
            int d = g * DG + t;
            #pragma unroll
            for (int k = 0; k < 5; k++) sw[t][k] = __ldg(W + d * 5 + k);
            sw[t][5] = __ldg(b + d);
        }
        __syncthreads();

        int f4 = chunk * 256 + t;
        if (f4 >= ROW4) return;
        int p = f4 * 4;

        float4* po = out + ((long)(stream * 256 + g * DG) * ROW4 + f4);
        const float4 ZZ = make_float4(0.f, 0.f, 0.f, 0.f);

        if (stream == 0) {
            if (f4 < 3750) {                  // p < 15000
                float4 c = __ldg((const float4*)x250 + f4);
                #pragma unroll 4
                for (int i = 0; i < DG; i++) {
                    float2 cd = *(const float2*)&sw[i][2];   // w2, w3
                    float2 ef = *(const float2*)&sw[i][4];   // w4, b
                    float w2 = cd.x, bb = ef.y;
                    float4 o;
                    o.x = fmaf(w2, c.x, bb);
                    o.y = fmaf(w2, c.y, bb);
                    o.z = fmaf(w2, c.z, bb);
                    o.w = fmaf(w2, c.w, bb);
                    __stcs(po, o);  po += ROW4;
                }
            } else {
                #pragma unroll 8
                for (int i = 0; i < DG; i++) { __stcs(po, ZZ); po += ROW4; }
            }
        } else if (stream == 1) {
            if (f4 < 7500) {                  // p < 30000
                float v0 = ldx(x500, p - 1, L500);
                float4 c = __ldg((const float4*)x500 + f4);
                float v5 = ldx(x500, p + 4, L500);
                #pragma unroll 4
                for (int i = 0; i < DG; i++) {
                    float2 ab = *(const float2*)&sw[i][0];
                    float2 cd = *(const float2*)&sw[i][2];
                    float2 ef = *(const float2*)&sw[i][4];
                    float w0 = ab.x, w2 = cd.x, w4 = ef.x, bb = ef.y;
                    float4 o;
                    o.x = fmaf(w0, v0,  fmaf(w2, c.x, fmaf(w4, c.y, bb)));
                    o.y = fmaf(w0, c.x, fmaf(w2, c.y, fmaf(w4, c.z, bb)));
                    o.z = fmaf(w0, c.y, fmaf(w2, c.z, fmaf(w4, c.w, bb)));
                    o.w = fmaf(w0, c.z, fmaf(w2, c.w, fmaf(w4, v5,  bb)));
                    __stcs(po, o);  po += ROW4;
                }
            } else {
                #pragma unroll 8
                for (int i = 0; i < DG; i++) { __stcs(po, ZZ); po += ROW4; }
            }
        } else {
            float u0 = ldx(x1000, p - 2, L1000);
            float u1 = ldx(x1000, p - 1, L1000);
            float4 c = __ldg((const float4*)x1000 + f4);
            float u6 = ldx(x1000, p + 4, L1000);
            float u7 = ldx(x1000, p + 5, L1000);
            #pragma unroll 4
            for (int i = 0; i < DG; i++) {
                float2 ab = *(const float2*)&sw[i][0];
                float2 cd = *(const float2*)&sw[i][2];
                float2 ef = *(const float2*)&sw[i][4];
                float4 o;
                o.x = fmaf(ab.x, u0,  fmaf(ab.y, u1,  fmaf(cd.x, c.x, fmaf(cd.y, c.y, fmaf(ef.x, c.z, ef.y)))));
                o.y = fmaf(ab.x, u1,  fmaf(ab.y, c.x, fmaf(cd.x, c.y, fmaf(cd.y, c.z, fmaf(ef.x, c.w, ef.y)))));
                o.z = fmaf(ab.x, c.x, fmaf(ab.y, c.y, fmaf(cd.x, c.z, fmaf(cd.y, c.w, fmaf(ef.x, u6,  ef.y)))));
                o.w = fmaf(ab.x, c.y, fmaf(ab.y, c.z, fmaf(cd.x, c.w, fmaf(cd.y, u6,  fmaf(ef.x, u7,  ef.y)))));
                __stcs(po, o);  po += ROW4;
            }
        }
    } else {
        // S = [rows(60000), cols(60000)] as float — store-only tail blocks
        int i = (blk - XBLOCKS) * 256 + threadIdx.x;
        if (i < S4TOT) {
            int e = i * 4;
            float4 o;
            float* pf = (float*)&o;
            if (e < L1000) {
                float r = (e < L250) ? 0.f : ((e < L250 + L500) ? 1.f : 2.f);
                o = make_float4(r, r, r, r);
            } else {
                int p = e - L1000;
                #pragma unroll
                for (int k = 0; k < 4; k++) {
                    int q = p + k;
                    float cc;
                    if (q < L250)             cc = (float)(q * 4);
                    else if (q < L250 + L500) cc = (float)((q - L250) * 2);
                    else                      cc = (float)(q - (L250 + L500));
                    pf[k] = cc;
                }
            }
            __stcs(out + X4TOT + i, o);
        }
    }
}

extern "C" void kernel_launch(void* const* d_in, const int* in_sizes, int n_in,
                              void* d_out, int out_size) {
    const float* x250  = (const float*)d_in[0];
    const float* x500  = (const float*)d_in[1];
    const float* x1000 = (const float*)d_in[2];
    const float* W     = (const float*)d_in[3];
    const float* b     = (const float*)d_in[4];
    float4* out = (float4*)d_out;

    embedder_kernel<<<XBLOCKS + SBLOCKS, 256>>>(x250, x500, x1000, W, b, out);
}